// round 1
// baseline (speedup 1.0000x reference)
#include <cuda_runtime.h>
#include <math.h>

#define NB       8192      // batch B
#define E_DIM    1024
#define P_DIM    512
#define D_DIM    1024      // 2P
#define M2       16384     // 2B rows in projection GEMM

// Scratch (no allocations allowed)
__device__ float g_zn[(size_t)NB * D_DIM];   // 32 MB, normalized embeddings [B, 2P]
__device__ float g_rowsum[NB];
__device__ float g_pos[NB];

// ---------------------------------------------------------------------------
// Kernel 1: Y = relu(Xview) @ W + b   (M=16384, N=512, K=1024)
// Row r<8192 -> x[r, 0:1024]; r>=8192 -> x[r-8192, 1024:2048].
// Output written into g_zn interleaved layout: zn[i, half*512 + n].
// ---------------------------------------------------------------------------
__global__ __launch_bounds__(256) void proj_kernel(const float* __restrict__ x,
                                                   const float* __restrict__ w,
                                                   const float* __restrict__ bias) {
    __shared__ float As[8][128];
    __shared__ float Bs[8][128];
    const int tid = threadIdx.x;
    const int ty = tid >> 4, tx = tid & 15;
    const int rowBase = blockIdx.y * 128;
    const int colBase = blockIdx.x * 128;

    const int aRow = tid >> 1;
    const int aK   = (tid & 1) * 4;
    const int gr = rowBase + aRow;
    const float* aPtr = x + (size_t)(gr & (NB - 1)) * 2048 + (size_t)(gr >> 13) * 1024;

    const int bK = tid >> 5;            // 0..7
    const int bN = (tid & 31) * 4;      // 0..124

    float acc[8][8];
#pragma unroll
    for (int i = 0; i < 8; i++)
#pragma unroll
        for (int j = 0; j < 8; j++) acc[i][j] = 0.f;

    for (int kb = 0; kb < E_DIM; kb += 8) {
        float4 av = *(const float4*)(aPtr + kb + aK);
        As[aK + 0][aRow] = fmaxf(av.x, 0.f);
        As[aK + 1][aRow] = fmaxf(av.y, 0.f);
        As[aK + 2][aRow] = fmaxf(av.z, 0.f);
        As[aK + 3][aRow] = fmaxf(av.w, 0.f);
        *(float4*)&Bs[bK][bN] =
            *(const float4*)(w + (size_t)(kb + bK) * P_DIM + colBase + bN);
        __syncthreads();
#pragma unroll
        for (int k = 0; k < 8; k++) {
            float a[8], bb[8];
            *(float4*)&a[0]  = *(const float4*)&As[k][ty * 8];
            *(float4*)&a[4]  = *(const float4*)&As[k][ty * 8 + 4];
            *(float4*)&bb[0] = *(const float4*)&Bs[k][tx * 8];
            *(float4*)&bb[4] = *(const float4*)&Bs[k][tx * 8 + 4];
#pragma unroll
            for (int i = 0; i < 8; i++)
#pragma unroll
                for (int j = 0; j < 8; j++)
                    acc[i][j] = fmaf(a[i], bb[j], acc[i][j]);
        }
        __syncthreads();
    }

#pragma unroll
    for (int i = 0; i < 8; i++) {
        const int r = rowBase + ty * 8 + i;
        const int ib = r & (NB - 1);
        const int half = r >> 13;
        float* outRow = g_zn + (size_t)ib * D_DIM + half * P_DIM;
#pragma unroll
        for (int j = 0; j < 8; j++) {
            const int c = colBase + tx * 8 + j;
            outRow[c] = acc[i][j] + bias[c];
        }
    }
}

// ---------------------------------------------------------------------------
// Kernel 2: per-row L2 normalize of g_zn [8192, 1024] in place
// ---------------------------------------------------------------------------
__global__ __launch_bounds__(256) void norm_kernel() {
    __shared__ float red[256];
    float* row = g_zn + (size_t)blockIdx.x * D_DIM;
    float4 v = *(float4*)(row + threadIdx.x * 4);
    red[threadIdx.x] = v.x * v.x + v.y * v.y + v.z * v.z + v.w * v.w;
    __syncthreads();
    for (int off = 128; off > 0; off >>= 1) {
        if (threadIdx.x < off) red[threadIdx.x] += red[threadIdx.x + off];
        __syncthreads();
    }
    const float inv = 1.0f / fmaxf(sqrtf(red[0]), 1e-8f);
    v.x *= inv; v.y *= inv; v.z *= inv; v.w *= inv;
    *(float4*)(row + threadIdx.x * 4) = v;
}

__global__ void zero_kernel() {
    const int i = blockIdx.x * blockDim.x + threadIdx.x;
    if (i < NB) g_rowsum[i] = 0.f;
}

// ---------------------------------------------------------------------------
// Kernel 3: fused  S = zn @ zn^T  tile  +  exp-sum per row (shift=10, diag
// skipped) + positive-pair capture at column i^4096. Never materializes S.
// ---------------------------------------------------------------------------
__global__ __launch_bounds__(256) void sim_kernel() {
    __shared__ float As[8][128];
    __shared__ float Bs[8][128];
    const int tid = threadIdx.x;
    const int ty = tid >> 4, tx = tid & 15;
    const int r0 = blockIdx.y * 128;
    const int c0 = blockIdx.x * 128;

    const int lRow = tid >> 1;
    const int lK   = (tid & 1) * 4;
    const float* aPtr = g_zn + (size_t)(r0 + lRow) * D_DIM;
    const float* bPtr = g_zn + (size_t)(c0 + lRow) * D_DIM;

    float acc[8][8];
#pragma unroll
    for (int i = 0; i < 8; i++)
#pragma unroll
        for (int j = 0; j < 8; j++) acc[i][j] = 0.f;

    for (int kb = 0; kb < D_DIM; kb += 8) {
        float4 av = *(const float4*)(aPtr + kb + lK);
        As[lK + 0][lRow] = av.x;
        As[lK + 1][lRow] = av.y;
        As[lK + 2][lRow] = av.z;
        As[lK + 3][lRow] = av.w;
        float4 bv = *(const float4*)(bPtr + kb + lK);
        Bs[lK + 0][lRow] = bv.x;
        Bs[lK + 1][lRow] = bv.y;
        Bs[lK + 2][lRow] = bv.z;
        Bs[lK + 3][lRow] = bv.w;
        __syncthreads();
#pragma unroll
        for (int k = 0; k < 8; k++) {
            float a[8], bb[8];
            *(float4*)&a[0]  = *(const float4*)&As[k][ty * 8];
            *(float4*)&a[4]  = *(const float4*)&As[k][ty * 8 + 4];
            *(float4*)&bb[0] = *(const float4*)&Bs[k][tx * 8];
            *(float4*)&bb[4] = *(const float4*)&Bs[k][tx * 8 + 4];
#pragma unroll
            for (int i = 0; i < 8; i++)
#pragma unroll
                for (int j = 0; j < 8; j++)
                    acc[i][j] = fmaf(a[i], bb[j], acc[i][j]);
        }
        __syncthreads();
    }

    // Epilogue: exp-sum per row; capture positive pair; skip diagonal.
    const bool hasPos  = (c0 >> 7) == ((r0 >> 7) ^ 32);  // 4096/128 == 32
    const bool hasDiag = (r0 == c0);
    float rowpart[8];
#pragma unroll
    for (int i = 0; i < 8; i++) rowpart[i] = 0.f;

#pragma unroll
    for (int i = 0; i < 8; i++) {
        const int r = r0 + ty * 8 + i;
#pragma unroll
        for (int j = 0; j < 8; j++) {
            const int c = c0 + tx * 8 + j;
            const float logit = acc[i][j] * 10.0f;
            if (hasPos && c == (r ^ 4096)) g_pos[r] = logit;
            float e = __expf(logit - 10.0f);
            if (hasDiag && r == c) e = 0.f;
            rowpart[i] += e;
        }
    }
    // reduce over the 16 tx-lanes (xor offsets stay inside 16-lane halves)
#pragma unroll
    for (int off = 8; off >= 1; off >>= 1)
#pragma unroll
        for (int i = 0; i < 8; i++)
            rowpart[i] += __shfl_xor_sync(0xffffffff, rowpart[i], off);

    if (tx == 0) {
#pragma unroll
        for (int i = 0; i < 8; i++)
            atomicAdd(&g_rowsum[r0 + ty * 8 + i], rowpart[i]);
    }
}

// ---------------------------------------------------------------------------
// Kernel 4: nll_i = -pos_i + 10 + log(rowsum_i); out = mean(nll)
// ---------------------------------------------------------------------------
__global__ __launch_bounds__(256) void final_kernel(float* __restrict__ out) {
    __shared__ float red[256];
    float s = 0.f;
    for (int i = threadIdx.x; i < NB; i += 256)
        s += -g_pos[i] + 10.0f + logf(g_rowsum[i]);
    red[threadIdx.x] = s;
    __syncthreads();
    for (int off = 128; off > 0; off >>= 1) {
        if (threadIdx.x < off) red[threadIdx.x] += red[threadIdx.x + off];
        __syncthreads();
    }
    if (threadIdx.x == 0) out[0] = red[0] / (float)NB;
}

// ---------------------------------------------------------------------------
extern "C" void kernel_launch(void* const* d_in, const int* in_sizes, int n_in,
                              void* d_out, int out_size) {
    const float* x = (const float*)d_in[0];
    const float* w = (const float*)d_in[1];
    const float* b = (const float*)d_in[2];
    float* out = (float*)d_out;

    dim3 g1(P_DIM / 128, M2 / 128);          // 4 x 128
    proj_kernel<<<g1, 256>>>(x, w, b);
    norm_kernel<<<NB, 256>>>();
    zero_kernel<<<(NB + 255) / 256, 256>>>();
    dim3 g2(NB / 128, NB / 128);             // 64 x 64
    sim_kernel<<<g2, 256>>>();
    final_kernel<<<1, 256>>>(out);
}

// round 3
// speedup vs baseline: 4.6734x; 4.6734x over previous
#include <cuda_runtime.h>
#include <cuda_bf16.h>
#include <math.h>
#include <stdint.h>

#define NB       8192      // batch B
#define E_DIM    1024
#define P_DIM    512
#define D_DIM    1024      // 2P
#define M2       16384     // 2B rows in projection GEMM

// Scratch (no allocations allowed)
__device__ float g_zn[(size_t)NB * D_DIM];              // 32 MB fp32 (proj output)
__device__ __nv_bfloat16 g_znh[(size_t)NB * D_DIM];     // 16 MB bf16 normalized
__device__ float g_rowsum[NB];
__device__ float g_pos[NB];

// ---------------------------------------------------------------------------
// PTX helpers (sm_80-era only: ldmatrix / mma.sync / cp.async — no 'a' features)
// ---------------------------------------------------------------------------
__device__ __forceinline__ uint32_t smem_u32(const void* p) {
    uint32_t a;
    asm("{ .reg .u64 t; cvta.to.shared.u64 t, %1; cvt.u32.u64 %0, t; }" : "=r"(a) : "l"(p));
    return a;
}

__device__ __forceinline__ void cp_async16(uint32_t dst, const void* src) {
    asm volatile("cp.async.cg.shared.global [%0], [%1], 16;" :: "r"(dst), "l"(src));
}
#define CP_COMMIT() asm volatile("cp.async.commit_group;" ::: "memory")
#define CP_WAIT2()  asm volatile("cp.async.wait_group 2;" ::: "memory")

__device__ __forceinline__ void ldsm_x4(uint32_t& r0, uint32_t& r1, uint32_t& r2,
                                        uint32_t& r3, uint32_t addr) {
    asm volatile("ldmatrix.sync.aligned.m8n8.x4.shared.b16 {%0,%1,%2,%3}, [%4];"
                 : "=r"(r0), "=r"(r1), "=r"(r2), "=r"(r3) : "r"(addr));
}

__device__ __forceinline__ void mma_bf16(float* c, const uint32_t* a, const uint32_t* b) {
    asm volatile(
        "mma.sync.aligned.m16n8k16.row.col.f32.bf16.bf16.f32 "
        "{%0,%1,%2,%3}, {%4,%5,%6,%7}, {%8,%9}, {%0,%1,%2,%3};"
        : "+f"(c[0]), "+f"(c[1]), "+f"(c[2]), "+f"(c[3])
        : "r"(a[0]), "r"(a[1]), "r"(a[2]), "r"(a[3]), "r"(b[0]), "r"(b[1]));
}

// ---------------------------------------------------------------------------
// Kernel 1: Y = relu(Xview) @ W + b   (M=16384, N=512, K=1024), fp32 SIMT
// ---------------------------------------------------------------------------
__global__ __launch_bounds__(256) void proj_kernel(const float* __restrict__ x,
                                                   const float* __restrict__ w,
                                                   const float* __restrict__ bias) {
    __shared__ float As[8][128];
    __shared__ float Bs[8][128];
    const int tid = threadIdx.x;
    const int ty = tid >> 4, tx = tid & 15;
    const int rowBase = blockIdx.y * 128;
    const int colBase = blockIdx.x * 128;

    const int aRow = tid >> 1;
    const int aK   = (tid & 1) * 4;
    const int gr = rowBase + aRow;
    const float* aPtr = x + (size_t)(gr & (NB - 1)) * 2048 + (size_t)(gr >> 13) * 1024;

    const int bK = tid >> 5;
    const int bN = (tid & 31) * 4;

    float acc[8][8];
#pragma unroll
    for (int i = 0; i < 8; i++)
#pragma unroll
        for (int j = 0; j < 8; j++) acc[i][j] = 0.f;

    for (int kb = 0; kb < E_DIM; kb += 8) {
        float4 av = *(const float4*)(aPtr + kb + aK);
        As[aK + 0][aRow] = fmaxf(av.x, 0.f);
        As[aK + 1][aRow] = fmaxf(av.y, 0.f);
        As[aK + 2][aRow] = fmaxf(av.z, 0.f);
        As[aK + 3][aRow] = fmaxf(av.w, 0.f);
        *(float4*)&Bs[bK][bN] =
            *(const float4*)(w + (size_t)(kb + bK) * P_DIM + colBase + bN);
        __syncthreads();
#pragma unroll
        for (int k = 0; k < 8; k++) {
            float a[8], bb[8];
            *(float4*)&a[0]  = *(const float4*)&As[k][ty * 8];
            *(float4*)&a[4]  = *(const float4*)&As[k][ty * 8 + 4];
            *(float4*)&bb[0] = *(const float4*)&Bs[k][tx * 8];
            *(float4*)&bb[4] = *(const float4*)&Bs[k][tx * 8 + 4];
#pragma unroll
            for (int i = 0; i < 8; i++)
#pragma unroll
                for (int j = 0; j < 8; j++)
                    acc[i][j] = fmaf(a[i], bb[j], acc[i][j]);
        }
        __syncthreads();
    }

#pragma unroll
    for (int i = 0; i < 8; i++) {
        const int r = rowBase + ty * 8 + i;
        const int ib = r & (NB - 1);
        const int half = r >> 13;
        float* outRow = g_zn + (size_t)ib * D_DIM + half * P_DIM;
#pragma unroll
        for (int j = 0; j < 8; j++) {
            const int c = colBase + tx * 8 + j;
            outRow[c] = acc[i][j] + bias[c];
        }
    }
}

// ---------------------------------------------------------------------------
// Kernel 2: per-row L2 normalize -> bf16 g_znh
// ---------------------------------------------------------------------------
__global__ __launch_bounds__(256) void norm_kernel() {
    __shared__ float red[256];
    const float* row = g_zn + (size_t)blockIdx.x * D_DIM;
    float4 v = *(const float4*)(row + threadIdx.x * 4);
    red[threadIdx.x] = v.x * v.x + v.y * v.y + v.z * v.z + v.w * v.w;
    __syncthreads();
    for (int off = 128; off > 0; off >>= 1) {
        if (threadIdx.x < off) red[threadIdx.x] += red[threadIdx.x + off];
        __syncthreads();
    }
    const float inv = 1.0f / fmaxf(sqrtf(red[0]), 1e-8f);
    __nv_bfloat16* outRow = g_znh + (size_t)blockIdx.x * D_DIM + threadIdx.x * 4;
    outRow[0] = __float2bfloat16(v.x * inv);
    outRow[1] = __float2bfloat16(v.y * inv);
    outRow[2] = __float2bfloat16(v.z * inv);
    outRow[3] = __float2bfloat16(v.w * inv);
}

__global__ void zero_kernel() {
    const int i = blockIdx.x * blockDim.x + threadIdx.x;
    if (i < NB) g_rowsum[i] = 0.f;
}

// ---------------------------------------------------------------------------
// Kernel 3: HMMA sim GEMM (upper triangle only) + fused softmax partials.
// Block tile 128x128, 8 warps (4x2), warp tile 32x64. BLOCK_K=32, 3-stage
// cp.async pipeline. Both operands are rows of g_znh (K-major) -> row.col mma.
// Off-diag tiles also scatter column-sums (symmetry).
// ---------------------------------------------------------------------------
#define ROW_BYTES   80            // 32 bf16 = 64B + 16B pad (conflict-free ldmatrix)
#define TILE_BYTES  (128 * ROW_BYTES)       // 10240
#define STAGE_BYTES (2 * TILE_BYTES)        // A + B = 20480
#define NUM_STAGES  3
#define SIM_SMEM    (NUM_STAGES * STAGE_BYTES)   // 61440
#define NUM_CHUNKS  (D_DIM / 32)            // 32

extern __shared__ char dsmem[];

__device__ __forceinline__ void prefetch_chunk(uint32_t stageA, uint32_t stageB,
                                               int r0, int c0, int kb, int tid) {
#pragma unroll
    for (int it = 0; it < 2; it++) {
        const int i = tid + it * 256;
        const int row = i >> 2, seg = i & 3;
        const uint32_t d = row * ROW_BYTES + seg * 16;
        cp_async16(stageA + d, g_znh + (((size_t)(r0 + row)) << 10) + kb + (seg << 3));
        cp_async16(stageB + d, g_znh + (((size_t)(c0 + row)) << 10) + kb + (seg << 3));
    }
}

__global__ __launch_bounds__(256)
void sim_kernel() {
    const int bx = blockIdx.x, by = blockIdx.y;
    if (bx < by) return;                       // upper triangle only
    const int tid = threadIdx.x;
    const int wid = tid >> 5;
    const int lane = tid & 31;
    const int warp_m = wid >> 1;               // 0..3 -> 32-row strips
    const int warp_n = wid & 1;                // 0..1 -> 64-col strips
    const int r0 = by * 128;
    const int c0 = bx * 128;

    const uint32_t sbase = smem_u32(dsmem);
    uint32_t stA[NUM_STAGES], stB[NUM_STAGES];
#pragma unroll
    for (int s = 0; s < NUM_STAGES; s++) {
        stA[s] = sbase + s * STAGE_BYTES;
        stB[s] = stA[s] + TILE_BYTES;
    }

    // ldmatrix per-lane base offsets
    const uint32_t aOff = (warp_m * 32 + (lane & 15)) * ROW_BYTES + (lane >> 4) * 16;
    const uint32_t bOff = (warp_n * 64 + ((lane >> 4) & 1) * 8 + (lane & 7)) * ROW_BYTES
                        + ((lane >> 3) & 1) * 16;

    float acc[2][8][4];
#pragma unroll
    for (int mi = 0; mi < 2; mi++)
#pragma unroll
        for (int ni = 0; ni < 8; ni++)
#pragma unroll
            for (int k = 0; k < 4; k++) acc[mi][ni][k] = 0.f;

    prefetch_chunk(stA[0], stB[0], r0, c0, 0, tid);  CP_COMMIT();
    prefetch_chunk(stA[1], stB[1], r0, c0, 32, tid); CP_COMMIT();

    for (int kc = 0; kc < NUM_CHUNKS; kc++) {
        if (kc + 2 < NUM_CHUNKS) {
            const int s = (kc + 2) % NUM_STAGES;
            prefetch_chunk(stA[s], stB[s], r0, c0, (kc + 2) * 32, tid);
        }
        CP_COMMIT();
        CP_WAIT2();
        __syncthreads();

        const int s = kc % NUM_STAGES;
#pragma unroll
        for (int ks = 0; ks < 2; ks++) {
            const uint32_t kofs = ks * 32;
            uint32_t a0[4], a1[4], bF[4][4];
            ldsm_x4(a0[0], a0[1], a0[2], a0[3], stA[s] + aOff + kofs);
            ldsm_x4(a1[0], a1[1], a1[2], a1[3], stA[s] + aOff + 16 * ROW_BYTES + kofs);
#pragma unroll
            for (int p = 0; p < 4; p++)
                ldsm_x4(bF[p][0], bF[p][1], bF[p][2], bF[p][3],
                        stB[s] + bOff + p * 16 * ROW_BYTES + kofs);
#pragma unroll
            for (int ni = 0; ni < 8; ni++) {
                mma_bf16(acc[0][ni], a0, &bF[ni >> 1][(ni & 1) * 2]);
                mma_bf16(acc[1][ni], a1, &bF[ni >> 1][(ni & 1) * 2]);
            }
        }
        __syncthreads();
    }

    // ---------------- fused epilogue ----------------
    const bool isDiag = (bx == by);
    const int rb = r0 + warp_m * 32 + (lane >> 2);
    const int cb = c0 + warp_n * 64 + (lane & 3) * 2;

#pragma unroll
    for (int mi = 0; mi < 2; mi++)
#pragma unroll
        for (int ni = 0; ni < 8; ni++)
#pragma unroll
            for (int k = 0; k < 4; k++) {
                const int r = rb + mi * 16 + (k >> 1) * 8;
                const int c = cb + ni * 8 + (k & 1);
                const float logit = acc[mi][ni][k] * 10.0f;
                if (c == (r ^ 4096)) { g_pos[r] = logit; g_pos[c] = logit; }
                float ev = __expf(logit - 10.0f);
                if (isDiag && r == c) ev = 0.f;
                acc[mi][ni][k] = ev;
            }

    // row sums: reduce over lane&3 (cols), one atomic per lane
    float rs[2][2] = {{0.f, 0.f}, {0.f, 0.f}};
#pragma unroll
    for (int mi = 0; mi < 2; mi++)
#pragma unroll
        for (int ni = 0; ni < 8; ni++) {
            rs[mi][0] += acc[mi][ni][0] + acc[mi][ni][1];
            rs[mi][1] += acc[mi][ni][2] + acc[mi][ni][3];
        }
#pragma unroll
    for (int off = 1; off <= 2; off <<= 1)
#pragma unroll
        for (int mi = 0; mi < 2; mi++)
#pragma unroll
            for (int h = 0; h < 2; h++)
                rs[mi][h] += __shfl_xor_sync(0xffffffffu, rs[mi][h], off);
    {
        const int combo = lane & 3;
        const int mi = combo >> 1, h = combo & 1;
        const int r = r0 + warp_m * 32 + mi * 16 + h * 8 + (lane >> 2);
        atomicAdd(&g_rowsum[r], rs[mi][h]);
    }

    // column sums (symmetric contribution), off-diag blocks only
    if (!isDiag) {
        float cs[8][2];
#pragma unroll
        for (int ni = 0; ni < 8; ni++)
#pragma unroll
            for (int h = 0; h < 2; h++)
                cs[ni][h] = acc[0][ni][h] + acc[0][ni][2 + h]
                          + acc[1][ni][h] + acc[1][ni][2 + h];
#pragma unroll
        for (int off = 4; off <= 16; off <<= 1)
#pragma unroll
            for (int ni = 0; ni < 8; ni++)
#pragma unroll
                for (int h = 0; h < 2; h++)
                    cs[ni][h] += __shfl_xor_sync(0xffffffffu, cs[ni][h], off);
        const int ni = lane >> 2;
        atomicAdd(&g_rowsum[cb + ni * 8 + 0], cs[ni][0]);
        atomicAdd(&g_rowsum[cb + ni * 8 + 1], cs[ni][1]);
    }
}

// ---------------------------------------------------------------------------
// Kernel 4: nll_i = -pos_i + 10 + log(rowsum_i); out = mean(nll)
// ---------------------------------------------------------------------------
__global__ __launch_bounds__(256) void final_kernel(float* __restrict__ out) {
    __shared__ float red[256];
    float s = 0.f;
    for (int i = threadIdx.x; i < NB; i += 256)
        s += -g_pos[i] + 10.0f + logf(g_rowsum[i]);
    red[threadIdx.x] = s;
    __syncthreads();
    for (int off = 128; off > 0; off >>= 1) {
        if (threadIdx.x < off) red[threadIdx.x] += red[threadIdx.x + off];
        __syncthreads();
    }
    if (threadIdx.x == 0) out[0] = red[0] / (float)NB;
}

// ---------------------------------------------------------------------------
extern "C" void kernel_launch(void* const* d_in, const int* in_sizes, int n_in,
                              void* d_out, int out_size) {
    const float* x = (const float*)d_in[0];
    const float* w = (const float*)d_in[1];
    const float* b = (const float*)d_in[2];
    float* out = (float*)d_out;

    cudaFuncSetAttribute(sim_kernel, cudaFuncAttributeMaxDynamicSharedMemorySize, SIM_SMEM);

    dim3 g1(P_DIM / 128, M2 / 128);
    proj_kernel<<<g1, 256>>>(x, w, b);
    norm_kernel<<<NB, 256>>>();
    zero_kernel<<<(NB + 255) / 256, 256>>>();
    dim3 g2(NB / 128, NB / 128);             // 64 x 64, lower triangle exits
    sim_kernel<<<g2, 256, SIM_SMEM>>>();
    final_kernel<<<1, 256>>>(out);
}

// round 4
// speedup vs baseline: 10.6370x; 2.2761x over previous
#include <cuda_runtime.h>
#include <cuda_bf16.h>
#include <math.h>
#include <stdint.h>

#define NB       8192      // batch B
#define E_DIM    1024
#define P_DIM    512
#define D_DIM    1024      // 2P
#define M2       16384     // 2B rows in projection GEMM

// Scratch (no allocations allowed)
__device__ float g_zn[(size_t)NB * D_DIM];              // 32 MB fp32 (proj output)
__device__ __nv_bfloat16 g_znh[(size_t)NB * D_DIM];     // 16 MB bf16 normalized
__device__ __nv_bfloat16 g_xh[(size_t)NB * 2 * E_DIM];  // 32 MB bf16 relu(x)
__device__ __nv_bfloat16 g_wh[(size_t)E_DIM * P_DIM];   // 1 MB bf16 w
__device__ float g_rowsum[NB];
__device__ float g_pos[NB];

// ---------------------------------------------------------------------------
// PTX helpers (sm_80-era only)
// ---------------------------------------------------------------------------
__device__ __forceinline__ uint32_t smem_u32(const void* p) {
    uint32_t a;
    asm("{ .reg .u64 t; cvta.to.shared.u64 t, %1; cvt.u32.u64 %0, t; }" : "=r"(a) : "l"(p));
    return a;
}
__device__ __forceinline__ void cp_async16(uint32_t dst, const void* src) {
    asm volatile("cp.async.cg.shared.global [%0], [%1], 16;" :: "r"(dst), "l"(src));
}
#define CP_COMMIT() asm volatile("cp.async.commit_group;" ::: "memory")
#define CP_WAIT2()  asm volatile("cp.async.wait_group 2;" ::: "memory")

__device__ __forceinline__ void ldsm_x4(uint32_t& r0, uint32_t& r1, uint32_t& r2,
                                        uint32_t& r3, uint32_t addr) {
    asm volatile("ldmatrix.sync.aligned.m8n8.x4.shared.b16 {%0,%1,%2,%3}, [%4];"
                 : "=r"(r0), "=r"(r1), "=r"(r2), "=r"(r3) : "r"(addr));
}
__device__ __forceinline__ void ldsm_x4_t(uint32_t& r0, uint32_t& r1, uint32_t& r2,
                                          uint32_t& r3, uint32_t addr) {
    asm volatile("ldmatrix.sync.aligned.m8n8.x4.trans.shared.b16 {%0,%1,%2,%3}, [%4];"
                 : "=r"(r0), "=r"(r1), "=r"(r2), "=r"(r3) : "r"(addr));
}
__device__ __forceinline__ void mma_bf16(float* c, const uint32_t* a, const uint32_t* b) {
    asm volatile(
        "mma.sync.aligned.m16n8k16.row.col.f32.bf16.bf16.f32 "
        "{%0,%1,%2,%3}, {%4,%5,%6,%7}, {%8,%9}, {%0,%1,%2,%3};"
        : "+f"(c[0]), "+f"(c[1]), "+f"(c[2]), "+f"(c[3])
        : "r"(a[0]), "r"(a[1]), "r"(a[2]), "r"(a[3]), "r"(b[0]), "r"(b[1]));
}

// ---------------------------------------------------------------------------
// Kernel 0: convert relu(x)->bf16 (g_xh) and w->bf16 (g_wh)
// ---------------------------------------------------------------------------
#define XCVT_BLOCKS 16384            // 8192*2048/4 elems / 256 thr
#define WCVT_BLOCKS 512              // 1024*512/4 / 256
__global__ __launch_bounds__(256) void convert_kernel(const float* __restrict__ x,
                                                      const float* __restrict__ w) {
    const int tid = threadIdx.x;
    if (blockIdx.x < XCVT_BLOCKS) {
        const size_t i = ((size_t)blockIdx.x * 256 + tid);
        float4 v = *(const float4*)(x + i * 4);
        __nv_bfloat162 p0 = __floats2bfloat162_rn(fmaxf(v.x, 0.f), fmaxf(v.y, 0.f));
        __nv_bfloat162 p1 = __floats2bfloat162_rn(fmaxf(v.z, 0.f), fmaxf(v.w, 0.f));
        uint2 o;
        o.x = *(uint32_t*)&p0; o.y = *(uint32_t*)&p1;
        *(uint2*)(g_xh + i * 4) = o;
    } else {
        const size_t i = ((size_t)(blockIdx.x - XCVT_BLOCKS) * 256 + tid);
        float4 v = *(const float4*)(w + i * 4);
        __nv_bfloat162 p0 = __floats2bfloat162_rn(v.x, v.y);
        __nv_bfloat162 p1 = __floats2bfloat162_rn(v.z, v.w);
        uint2 o;
        o.x = *(uint32_t*)&p0; o.y = *(uint32_t*)&p1;
        *(uint2*)(g_wh + i * 4) = o;
    }
}

// ---------------------------------------------------------------------------
// Kernel 1: HMMA projection  Y = relu(X) @ W + b  (M=16384, N=512, K=1024)
// Block 128x128, warps 4x2 (warp tile 32x64), BK=32, 3-stage cp.async.
// A (g_xh rows) K-major; B (g_wh) stored [k][n] -> ldmatrix.trans.
// ---------------------------------------------------------------------------
#define AROW_BYTES  80                       // 32 bf16 + 16B pad
#define PA_BYTES    (128 * AROW_BYTES)       // 10240
#define BROW_BYTES  272                      // 128 bf16 (256B) + 16B pad
#define PB_BYTES    (32 * BROW_BYTES)        // 8704
#define PSTAGE      (PA_BYTES + PB_BYTES)    // 18944
#define PROJ_SMEM   (3 * PSTAGE)             // 56832
#define PCHUNKS     (E_DIM / 32)             // 32

extern __shared__ char dsmem[];

__device__ __forceinline__ void proj_prefetch(uint32_t stA, uint32_t stB,
                                              int m0, int n0, int kb, int tid) {
    // A: 128 rows x 64B  (512 chunks of 16B)
    {
        const int i = tid;                   // 0..255 -> two iters
#pragma unroll
        for (int it = 0; it < 2; it++) {
            const int j = i + it * 256;
            const int row = j >> 2, seg = j & 3;
            const int r = m0 + row;
            const __nv_bfloat16* src = g_xh + (size_t)(r & (NB - 1)) * 2048
                                     + (size_t)(r >> 13) * 1024 + kb + (seg << 3);
            cp_async16(stA + row * AROW_BYTES + seg * 16, src);
        }
    }
    // B: 32 k-rows x 256B (512 chunks of 16B)
#pragma unroll
    for (int it = 0; it < 2; it++) {
        const int j = tid + it * 256;
        const int row = j >> 4, seg = j & 15;
        const __nv_bfloat16* src = g_wh + (size_t)(kb + row) * P_DIM + n0 + (seg << 3);
        cp_async16(stB + row * BROW_BYTES + seg * 16, src);
    }
}

__global__ __launch_bounds__(256)
void proj_kernel(const float* __restrict__ bias) {
    const int tid = threadIdx.x;
    const int wid = tid >> 5;
    const int lane = tid & 31;
    const int warp_m = wid >> 1;             // 0..3
    const int warp_n = wid & 1;              // 0..1
    const int m0 = blockIdx.y * 128;
    const int n0 = blockIdx.x * 128;

    const uint32_t sbase = smem_u32(dsmem);
    uint32_t stA[3], stB[3];
#pragma unroll
    for (int s = 0; s < 3; s++) {
        stA[s] = sbase + s * PSTAGE;
        stB[s] = stA[s] + PA_BYTES;
    }

    const uint32_t aOff = (warp_m * 32 + (lane & 15)) * AROW_BYTES + (lane >> 4) * 16;
    // B trans ldmatrix lane address: k-row = (lane&7) + ((lane>>3)&1)*8, n-col += (lane>>4)*8
    const uint32_t bRow = (lane & 7) + ((lane >> 3) & 1) * 8;
    const uint32_t bCol = warp_n * 64 + (lane >> 4) * 8;

    float acc[2][8][4];
#pragma unroll
    for (int mi = 0; mi < 2; mi++)
#pragma unroll
        for (int ni = 0; ni < 8; ni++)
#pragma unroll
            for (int k = 0; k < 4; k++) acc[mi][ni][k] = 0.f;

    proj_prefetch(stA[0], stB[0], m0, n0, 0, tid);  CP_COMMIT();
    proj_prefetch(stA[1], stB[1], m0, n0, 32, tid); CP_COMMIT();

    for (int kc = 0; kc < PCHUNKS; kc++) {
        if (kc + 2 < PCHUNKS) {
            const int s = (kc + 2) % 3;
            proj_prefetch(stA[s], stB[s], m0, n0, (kc + 2) * 32, tid);
        }
        CP_COMMIT();
        CP_WAIT2();
        __syncthreads();

        const int s = kc % 3;
#pragma unroll
        for (int ks = 0; ks < 2; ks++) {
            uint32_t a0[4], a1[4], bF[4][4];
            ldsm_x4(a0[0], a0[1], a0[2], a0[3], stA[s] + aOff + ks * 32);
            ldsm_x4(a1[0], a1[1], a1[2], a1[3], stA[s] + aOff + 16 * AROW_BYTES + ks * 32);
#pragma unroll
            for (int p = 0; p < 4; p++)
                ldsm_x4_t(bF[p][0], bF[p][1], bF[p][2], bF[p][3],
                          stB[s] + (ks * 16 + bRow) * BROW_BYTES + (bCol + p * 16) * 2);
#pragma unroll
            for (int ni = 0; ni < 8; ni++) {
                mma_bf16(acc[0][ni], a0, &bF[ni >> 1][(ni & 1) * 2]);
                mma_bf16(acc[1][ni], a1, &bF[ni >> 1][(ni & 1) * 2]);
            }
        }
        __syncthreads();
    }

    // epilogue: + bias, store fp32 to g_zn (interleaved layout)
    const int rb = m0 + warp_m * 32 + (lane >> 2);
    const int cb = n0 + warp_n * 64 + (lane & 3) * 2;
#pragma unroll
    for (int mi = 0; mi < 2; mi++)
#pragma unroll
        for (int half8 = 0; half8 < 2; half8++) {
            const int r = rb + mi * 16 + half8 * 8;
            const int ib = r & (NB - 1);
            const int hh = r >> 13;
            float* outRow = g_zn + (size_t)ib * D_DIM + hh * P_DIM;
#pragma unroll
            for (int ni = 0; ni < 8; ni++) {
                const int c = cb + ni * 8;
                float2 v;
                v.x = acc[mi][ni][half8 * 2 + 0] + __ldg(bias + c);
                v.y = acc[mi][ni][half8 * 2 + 1] + __ldg(bias + c + 1);
                *(float2*)(outRow + c) = v;
            }
        }
}

// ---------------------------------------------------------------------------
// Kernel 2: per-row L2 normalize -> bf16 g_znh (also zeroes g_rowsum)
// ---------------------------------------------------------------------------
__global__ __launch_bounds__(256) void norm_kernel() {
    __shared__ float red[256];
    const float* row = g_zn + (size_t)blockIdx.x * D_DIM;
    float4 v = *(const float4*)(row + threadIdx.x * 4);
    red[threadIdx.x] = v.x * v.x + v.y * v.y + v.z * v.z + v.w * v.w;
    __syncthreads();
    for (int off = 128; off > 0; off >>= 1) {
        if (threadIdx.x < off) red[threadIdx.x] += red[threadIdx.x + off];
        __syncthreads();
    }
    const float inv = 1.0f / fmaxf(sqrtf(red[0]), 1e-8f);
    __nv_bfloat162 p0 = __floats2bfloat162_rn(v.x * inv, v.y * inv);
    __nv_bfloat162 p1 = __floats2bfloat162_rn(v.z * inv, v.w * inv);
    uint2 o;
    o.x = *(uint32_t*)&p0; o.y = *(uint32_t*)&p1;
    *(uint2*)(g_znh + (size_t)blockIdx.x * D_DIM + threadIdx.x * 4) = o;
    if (threadIdx.x == 0) g_rowsum[blockIdx.x] = 0.f;
}

// ---------------------------------------------------------------------------
// Kernel 3: HMMA sim GEMM (upper triangle, 1D grid) + fused softmax partials
// ---------------------------------------------------------------------------
#define ROW_BYTES   80
#define TILE_BYTES  (128 * ROW_BYTES)
#define STAGE_BYTES (2 * TILE_BYTES)
#define SIM_SMEM    (3 * STAGE_BYTES)
#define NUM_CHUNKS  (D_DIM / 32)
#define TRI_BLOCKS  2080                      // 64*65/2

__device__ __forceinline__ void sim_prefetch(uint32_t stageA, uint32_t stageB,
                                             int r0, int c0, int kb, int tid) {
#pragma unroll
    for (int it = 0; it < 2; it++) {
        const int i = tid + it * 256;
        const int row = i >> 2, seg = i & 3;
        const uint32_t d = row * ROW_BYTES + seg * 16;
        cp_async16(stageA + d, g_znh + (((size_t)(r0 + row)) << 10) + kb + (seg << 3));
        cp_async16(stageB + d, g_znh + (((size_t)(c0 + row)) << 10) + kb + (seg << 3));
    }
}

__global__ __launch_bounds__(256)
void sim_kernel() {
    // map t -> (by, bx) upper triangle, bx >= by
    const int t = blockIdx.x;
    int by = (int)((129.0f - sqrtf(129.0f * 129.0f - 8.0f * (float)t)) * 0.5f);
    if (by > 63) by = 63;
    if (by < 0) by = 0;
    while (by * 64 - (by * (by - 1)) / 2 > t) by--;
    while ((by + 1) * 64 - ((by + 1) * by) / 2 <= t) by++;
    const int bx = by + (t - (by * 64 - (by * (by - 1)) / 2));

    const int tid = threadIdx.x;
    const int wid = tid >> 5;
    const int lane = tid & 31;
    const int warp_m = wid >> 1;
    const int warp_n = wid & 1;
    const int r0 = by * 128;
    const int c0 = bx * 128;

    const uint32_t sbase = smem_u32(dsmem);
    uint32_t stA[3], stB[3];
#pragma unroll
    for (int s = 0; s < 3; s++) {
        stA[s] = sbase + s * STAGE_BYTES;
        stB[s] = stA[s] + TILE_BYTES;
    }

    const uint32_t aOff = (warp_m * 32 + (lane & 15)) * ROW_BYTES + (lane >> 4) * 16;
    const uint32_t bOff = (warp_n * 64 + ((lane >> 4) & 1) * 8 + (lane & 7)) * ROW_BYTES
                        + ((lane >> 3) & 1) * 16;

    float acc[2][8][4];
#pragma unroll
    for (int mi = 0; mi < 2; mi++)
#pragma unroll
        for (int ni = 0; ni < 8; ni++)
#pragma unroll
            for (int k = 0; k < 4; k++) acc[mi][ni][k] = 0.f;

    sim_prefetch(stA[0], stB[0], r0, c0, 0, tid);  CP_COMMIT();
    sim_prefetch(stA[1], stB[1], r0, c0, 32, tid); CP_COMMIT();

    for (int kc = 0; kc < NUM_CHUNKS; kc++) {
        if (kc + 2 < NUM_CHUNKS) {
            const int s = (kc + 2) % 3;
            sim_prefetch(stA[s], stB[s], r0, c0, (kc + 2) * 32, tid);
        }
        CP_COMMIT();
        CP_WAIT2();
        __syncthreads();

        const int s = kc % 3;
#pragma unroll
        for (int ks = 0; ks < 2; ks++) {
            const uint32_t kofs = ks * 32;
            uint32_t a0[4], a1[4], bF[4][4];
            ldsm_x4(a0[0], a0[1], a0[2], a0[3], stA[s] + aOff + kofs);
            ldsm_x4(a1[0], a1[1], a1[2], a1[3], stA[s] + aOff + 16 * ROW_BYTES + kofs);
#pragma unroll
            for (int p = 0; p < 4; p++)
                ldsm_x4(bF[p][0], bF[p][1], bF[p][2], bF[p][3],
                        stB[s] + bOff + p * 16 * ROW_BYTES + kofs);
#pragma unroll
            for (int ni = 0; ni < 8; ni++) {
                mma_bf16(acc[0][ni], a0, &bF[ni >> 1][(ni & 1) * 2]);
                mma_bf16(acc[1][ni], a1, &bF[ni >> 1][(ni & 1) * 2]);
            }
        }
        __syncthreads();
    }

    // ---------------- fused epilogue ----------------
    const bool isDiag = (bx == by);
    const int rb = r0 + warp_m * 32 + (lane >> 2);
    const int cb = c0 + warp_n * 64 + (lane & 3) * 2;

#pragma unroll
    for (int mi = 0; mi < 2; mi++)
#pragma unroll
        for (int ni = 0; ni < 8; ni++)
#pragma unroll
            for (int k = 0; k < 4; k++) {
                const int r = rb + mi * 16 + (k >> 1) * 8;
                const int c = cb + ni * 8 + (k & 1);
                const float logit = acc[mi][ni][k] * 10.0f;
                if (c == (r ^ 4096)) { g_pos[r] = logit; g_pos[c] = logit; }
                float ev = __expf(logit - 10.0f);
                if (isDiag && r == c) ev = 0.f;
                acc[mi][ni][k] = ev;
            }

    float rs[2][2] = {{0.f, 0.f}, {0.f, 0.f}};
#pragma unroll
    for (int mi = 0; mi < 2; mi++)
#pragma unroll
        for (int ni = 0; ni < 8; ni++) {
            rs[mi][0] += acc[mi][ni][0] + acc[mi][ni][1];
            rs[mi][1] += acc[mi][ni][2] + acc[mi][ni][3];
        }
#pragma unroll
    for (int off = 1; off <= 2; off <<= 1)
#pragma unroll
        for (int mi = 0; mi < 2; mi++)
#pragma unroll
            for (int h = 0; h < 2; h++)
                rs[mi][h] += __shfl_xor_sync(0xffffffffu, rs[mi][h], off);
    {
        const int combo = lane & 3;
        const int mi = combo >> 1, h = combo & 1;
        const int r = r0 + warp_m * 32 + mi * 16 + h * 8 + (lane >> 2);
        atomicAdd(&g_rowsum[r], rs[mi][h]);
    }

    if (!isDiag) {
        float cs[8][2];
#pragma unroll
        for (int ni = 0; ni < 8; ni++)
#pragma unroll
            for (int h = 0; h < 2; h++)
                cs[ni][h] = acc[0][ni][h] + acc[0][ni][2 + h]
                          + acc[1][ni][h] + acc[1][ni][2 + h];
#pragma unroll
        for (int off = 4; off <= 16; off <<= 1)
#pragma unroll
            for (int ni = 0; ni < 8; ni++)
#pragma unroll
                for (int h = 0; h < 2; h++)
                    cs[ni][h] += __shfl_xor_sync(0xffffffffu, cs[ni][h], off);
        const int ni = lane >> 2;
        atomicAdd(&g_rowsum[cb + ni * 8 + 0], cs[ni][0]);
        atomicAdd(&g_rowsum[cb + ni * 8 + 1], cs[ni][1]);
    }
}

// ---------------------------------------------------------------------------
// Kernel 4: nll_i = -pos_i + 10 + log(rowsum_i); out = mean(nll)
// ---------------------------------------------------------------------------
__global__ __launch_bounds__(256) void final_kernel(float* __restrict__ out) {
    __shared__ float red[256];
    float s = 0.f;
    for (int i = threadIdx.x; i < NB; i += 256)
        s += -g_pos[i] + 10.0f + logf(g_rowsum[i]);
    red[threadIdx.x] = s;
    __syncthreads();
    for (int off = 128; off > 0; off >>= 1) {
        if (threadIdx.x < off) red[threadIdx.x] += red[threadIdx.x + off];
        __syncthreads();
    }
    if (threadIdx.x == 0) out[0] = red[0] / (float)NB;
}

// ---------------------------------------------------------------------------
extern "C" void kernel_launch(void* const* d_in, const int* in_sizes, int n_in,
                              void* d_out, int out_size) {
    const float* x = (const float*)d_in[0];
    const float* w = (const float*)d_in[1];
    const float* b = (const float*)d_in[2];
    float* out = (float*)d_out;

    cudaFuncSetAttribute(proj_kernel, cudaFuncAttributeMaxDynamicSharedMemorySize, PROJ_SMEM);
    cudaFuncSetAttribute(sim_kernel,  cudaFuncAttributeMaxDynamicSharedMemorySize, SIM_SMEM);

    convert_kernel<<<XCVT_BLOCKS + WCVT_BLOCKS, 256>>>(x, w);
    dim3 g1(P_DIM / 128, M2 / 128);          // 4 x 128
    proj_kernel<<<g1, 256, PROJ_SMEM>>>(b);
    norm_kernel<<<NB, 256>>>();
    sim_kernel<<<TRI_BLOCKS, 256, SIM_SMEM>>>();
    final_kernel<<<1, 256>>>(out);
}

// round 5
// speedup vs baseline: 11.1023x; 1.0437x over previous
#include <cuda_runtime.h>
#include <cuda_bf16.h>
#include <math.h>
#include <stdint.h>

#define NB       8192      // batch B
#define E_DIM    1024
#define P_DIM    512
#define D_DIM    1024      // 2P
#define M2       16384     // 2B rows in projection GEMM

// Scratch (no allocations allowed)
__device__ float g_zn[(size_t)NB * D_DIM];              // 32 MB fp32 (proj output)
__device__ __nv_bfloat16 g_znh[(size_t)NB * D_DIM];     // 16 MB bf16 normalized
__device__ __nv_bfloat16 g_xh[(size_t)NB * 2 * E_DIM];  // 32 MB bf16 relu(x)
__device__ __nv_bfloat16 g_wh[(size_t)E_DIM * P_DIM];   // 1 MB bf16 w
__device__ float g_rowsum[NB];
__device__ float g_pos[NB];

// ---------------------------------------------------------------------------
// PTX helpers (sm_80-era only)
// ---------------------------------------------------------------------------
__device__ __forceinline__ uint32_t smem_u32(const void* p) {
    uint32_t a;
    asm("{ .reg .u64 t; cvta.to.shared.u64 t, %1; cvt.u32.u64 %0, t; }" : "=r"(a) : "l"(p));
    return a;
}
__device__ __forceinline__ void cp_async16(uint32_t dst, const void* src) {
    asm volatile("cp.async.cg.shared.global [%0], [%1], 16;" :: "r"(dst), "l"(src));
}
#define CP_COMMIT() asm volatile("cp.async.commit_group;" ::: "memory")
#define CP_WAIT(N)  asm volatile("cp.async.wait_group %0;" :: "n"(N) : "memory")

__device__ __forceinline__ void ldsm_x4(uint32_t& r0, uint32_t& r1, uint32_t& r2,
                                        uint32_t& r3, uint32_t addr) {
    asm volatile("ldmatrix.sync.aligned.m8n8.x4.shared.b16 {%0,%1,%2,%3}, [%4];"
                 : "=r"(r0), "=r"(r1), "=r"(r2), "=r"(r3) : "r"(addr));
}
__device__ __forceinline__ void ldsm_x4_t(uint32_t& r0, uint32_t& r1, uint32_t& r2,
                                          uint32_t& r3, uint32_t addr) {
    asm volatile("ldmatrix.sync.aligned.m8n8.x4.trans.shared.b16 {%0,%1,%2,%3}, [%4];"
                 : "=r"(r0), "=r"(r1), "=r"(r2), "=r"(r3) : "r"(addr));
}
__device__ __forceinline__ void mma_bf16(float* c, const uint32_t* a, const uint32_t* b) {
    asm volatile(
        "mma.sync.aligned.m16n8k16.row.col.f32.bf16.bf16.f32 "
        "{%0,%1,%2,%3}, {%4,%5,%6,%7}, {%8,%9}, {%0,%1,%2,%3};"
        : "+f"(c[0]), "+f"(c[1]), "+f"(c[2]), "+f"(c[3])
        : "r"(a[0]), "r"(a[1]), "r"(a[2]), "r"(a[3]), "r"(b[0]), "r"(b[1]));
}

// ---------------------------------------------------------------------------
// Kernel 0: convert relu(x)->bf16 (g_xh) and w->bf16 (g_wh)
// ---------------------------------------------------------------------------
#define XCVT_BLOCKS 16384
#define WCVT_BLOCKS 512
__global__ __launch_bounds__(256) void convert_kernel(const float* __restrict__ x,
                                                      const float* __restrict__ w) {
    const int tid = threadIdx.x;
    if (blockIdx.x < XCVT_BLOCKS) {
        const size_t i = ((size_t)blockIdx.x * 256 + tid);
        float4 v = *(const float4*)(x + i * 4);
        __nv_bfloat162 p0 = __floats2bfloat162_rn(fmaxf(v.x, 0.f), fmaxf(v.y, 0.f));
        __nv_bfloat162 p1 = __floats2bfloat162_rn(fmaxf(v.z, 0.f), fmaxf(v.w, 0.f));
        uint2 o; o.x = *(uint32_t*)&p0; o.y = *(uint32_t*)&p1;
        *(uint2*)(g_xh + i * 4) = o;
    } else {
        const size_t i = ((size_t)(blockIdx.x - XCVT_BLOCKS) * 256 + tid);
        float4 v = *(const float4*)(w + i * 4);
        __nv_bfloat162 p0 = __floats2bfloat162_rn(v.x, v.y);
        __nv_bfloat162 p1 = __floats2bfloat162_rn(v.z, v.w);
        uint2 o; o.x = *(uint32_t*)&p0; o.y = *(uint32_t*)&p1;
        *(uint2*)(g_wh + i * 4) = o;
    }
}

// ---------------------------------------------------------------------------
// Kernel 1: HMMA projection, block 128x128, 4 warps (warp tile 64x64),
// BK=32, 4-stage cp.async, single-sync mainloop.
// ---------------------------------------------------------------------------
#define AROW_BYTES  80
#define PA_BYTES    (128 * AROW_BYTES)       // 10240
#define BROW_BYTES  272                      // 128 bf16 + 16B pad
#define PB_BYTES    (32 * BROW_BYTES)        // 8704
#define PSTAGE      (PA_BYTES + PB_BYTES)    // 18944
#define PSTAGES     4
#define PROJ_SMEM   (PSTAGES * PSTAGE)       // 75776
#define PCHUNKS     (E_DIM / 32)             // 32

extern __shared__ char dsmem[];

__device__ __forceinline__ void proj_prefetch(uint32_t stA, uint32_t stB,
                                              int m0, int n0, int kb, int tid) {
#pragma unroll
    for (int it = 0; it < 4; it++) {        // A: 128 rows x 4 segs
        const int j = tid + it * 128;
        const int row = j >> 2, seg = j & 3;
        const int r = m0 + row;
        const __nv_bfloat16* src = g_xh + (size_t)(r & (NB - 1)) * 2048
                                 + (size_t)(r >> 13) * 1024 + kb + (seg << 3);
        cp_async16(stA + row * AROW_BYTES + seg * 16, src);
    }
#pragma unroll
    for (int it = 0; it < 4; it++) {        // B: 32 k-rows x 16 segs
        const int j = tid + it * 128;
        const int row = j >> 4, seg = j & 15;
        const __nv_bfloat16* src = g_wh + (size_t)(kb + row) * P_DIM + n0 + (seg << 3);
        cp_async16(stB + row * BROW_BYTES + seg * 16, src);
    }
}

__global__ __launch_bounds__(128)
void proj_kernel(const float* __restrict__ bias) {
    const int tid = threadIdx.x;
    const int wid = tid >> 5;
    const int lane = tid & 31;
    const int warp_m = wid >> 1;             // 0..1 -> 64-row strips
    const int warp_n = wid & 1;              // 0..1 -> 64-col strips
    const int m0 = blockIdx.y * 128;
    const int n0 = blockIdx.x * 128;

    const uint32_t sbase = smem_u32(dsmem);
    uint32_t stA[PSTAGES], stB[PSTAGES];
#pragma unroll
    for (int s = 0; s < PSTAGES; s++) {
        stA[s] = sbase + s * PSTAGE;
        stB[s] = stA[s] + PA_BYTES;
    }

    const uint32_t aOff = (warp_m * 64 + (lane & 15)) * AROW_BYTES + (lane >> 4) * 16;
    const uint32_t bRow = (lane & 7) + ((lane >> 3) & 1) * 8;
    const uint32_t bCol = warp_n * 64 + (lane >> 4) * 8;

    float acc[4][8][4];
#pragma unroll
    for (int mi = 0; mi < 4; mi++)
#pragma unroll
        for (int ni = 0; ni < 8; ni++)
#pragma unroll
            for (int k = 0; k < 4; k++) acc[mi][ni][k] = 0.f;

    proj_prefetch(stA[0], stB[0], m0, n0, 0, tid);  CP_COMMIT();
    proj_prefetch(stA[1], stB[1], m0, n0, 32, tid); CP_COMMIT();
    proj_prefetch(stA[2], stB[2], m0, n0, 64, tid); CP_COMMIT();

    for (int kc = 0; kc < PCHUNKS; kc++) {
        CP_WAIT(2);
        __syncthreads();
        if (kc + 3 < PCHUNKS) {
            const int s = (kc + 3) % PSTAGES;
            proj_prefetch(stA[s], stB[s], m0, n0, (kc + 3) * 32, tid);
        }
        CP_COMMIT();

        const int s = kc % PSTAGES;
#pragma unroll
        for (int ks = 0; ks < 2; ks++) {
            uint32_t aF[4][4], bF[4][4];
#pragma unroll
            for (int mi = 0; mi < 4; mi++)
                ldsm_x4(aF[mi][0], aF[mi][1], aF[mi][2], aF[mi][3],
                        stA[s] + aOff + mi * 16 * AROW_BYTES + ks * 32);
#pragma unroll
            for (int p = 0; p < 4; p++)
                ldsm_x4_t(bF[p][0], bF[p][1], bF[p][2], bF[p][3],
                          stB[s] + (ks * 16 + bRow) * BROW_BYTES + (bCol + p * 16) * 2);
#pragma unroll
            for (int mi = 0; mi < 4; mi++)
#pragma unroll
                for (int ni = 0; ni < 8; ni++)
                    mma_bf16(acc[mi][ni], aF[mi], &bF[ni >> 1][(ni & 1) * 2]);
        }
    }

    // epilogue: + bias, store fp32 to g_zn (interleaved layout)
    const int cb = n0 + warp_n * 64 + (lane & 3) * 2;
#pragma unroll
    for (int mi = 0; mi < 4; mi++)
#pragma unroll
        for (int half8 = 0; half8 < 2; half8++) {
            const int r = m0 + warp_m * 64 + mi * 16 + half8 * 8 + (lane >> 2);
            const int ib = r & (NB - 1);
            const int hh = r >> 13;
            float* outRow = g_zn + (size_t)ib * D_DIM + hh * P_DIM;
#pragma unroll
            for (int ni = 0; ni < 8; ni++) {
                const int c = cb + ni * 8;
                float2 v;
                v.x = acc[mi][ni][half8 * 2 + 0] + __ldg(bias + c);
                v.y = acc[mi][ni][half8 * 2 + 1] + __ldg(bias + c + 1);
                *(float2*)(outRow + c) = v;
            }
        }
}

// ---------------------------------------------------------------------------
// Kernel 2: per-row L2 normalize -> bf16 g_znh (also zeroes g_rowsum)
// ---------------------------------------------------------------------------
__global__ __launch_bounds__(256) void norm_kernel() {
    __shared__ float red[256];
    const float* row = g_zn + (size_t)blockIdx.x * D_DIM;
    float4 v = *(const float4*)(row + threadIdx.x * 4);
    red[threadIdx.x] = v.x * v.x + v.y * v.y + v.z * v.z + v.w * v.w;
    __syncthreads();
    for (int off = 128; off > 0; off >>= 1) {
        if (threadIdx.x < off) red[threadIdx.x] += red[threadIdx.x + off];
        __syncthreads();
    }
    const float inv = 1.0f / fmaxf(sqrtf(red[0]), 1e-8f);
    __nv_bfloat162 p0 = __floats2bfloat162_rn(v.x * inv, v.y * inv);
    __nv_bfloat162 p1 = __floats2bfloat162_rn(v.z * inv, v.w * inv);
    uint2 o; o.x = *(uint32_t*)&p0; o.y = *(uint32_t*)&p1;
    *(uint2*)(g_znh + (size_t)blockIdx.x * D_DIM + threadIdx.x * 4) = o;
    if (threadIdx.x == 0) g_rowsum[blockIdx.x] = 0.f;
}

// ---------------------------------------------------------------------------
// Kernel 3: HMMA sim GEMM (upper triangle), block 128x128, 4 warps (64x64),
// 4-stage cp.async, single-sync mainloop, fused softmax partials.
// ---------------------------------------------------------------------------
#define ROW_BYTES   80
#define TILE_BYTES  (128 * ROW_BYTES)        // 10240
#define STAGE_BYTES (2 * TILE_BYTES)         // 20480
#define SSTAGES     4
#define SIM_SMEM    (SSTAGES * STAGE_BYTES)  // 81920
#define NUM_CHUNKS  (D_DIM / 32)             // 32
#define TRI_BLOCKS  2080                     // 64*65/2

__device__ __forceinline__ void sim_prefetch(uint32_t stageA, uint32_t stageB,
                                             int r0, int c0, int kb, int tid) {
#pragma unroll
    for (int it = 0; it < 4; it++) {
        const int i = tid + it * 128;
        const int row = i >> 2, seg = i & 3;
        const uint32_t d = row * ROW_BYTES + seg * 16;
        cp_async16(stageA + d, g_znh + (((size_t)(r0 + row)) << 10) + kb + (seg << 3));
        cp_async16(stageB + d, g_znh + (((size_t)(c0 + row)) << 10) + kb + (seg << 3));
    }
}

__global__ __launch_bounds__(128)
void sim_kernel() {
    // map t -> (by, bx) upper triangle, bx >= by
    const int t = blockIdx.x;
    int by = (int)((129.0f - sqrtf(129.0f * 129.0f - 8.0f * (float)t)) * 0.5f);
    if (by > 63) by = 63;
    if (by < 0) by = 0;
    while (by * 64 - (by * (by - 1)) / 2 > t) by--;
    while ((by + 1) * 64 - ((by + 1) * by) / 2 <= t) by++;
    const int bx = by + (t - (by * 64 - (by * (by - 1)) / 2));

    const int tid = threadIdx.x;
    const int wid = tid >> 5;
    const int lane = tid & 31;
    const int warp_m = wid >> 1;
    const int warp_n = wid & 1;
    const int r0 = by * 128;
    const int c0 = bx * 128;

    const uint32_t sbase = smem_u32(dsmem);
    uint32_t stA[SSTAGES], stB[SSTAGES];
#pragma unroll
    for (int s = 0; s < SSTAGES; s++) {
        stA[s] = sbase + s * STAGE_BYTES;
        stB[s] = stA[s] + TILE_BYTES;
    }

    const uint32_t aOff = (warp_m * 64 + (lane & 15)) * ROW_BYTES + (lane >> 4) * 16;
    const uint32_t bOff = (warp_n * 64 + ((lane >> 4) & 1) * 8 + (lane & 7)) * ROW_BYTES
                        + ((lane >> 3) & 1) * 16;

    float acc[4][8][4];
#pragma unroll
    for (int mi = 0; mi < 4; mi++)
#pragma unroll
        for (int ni = 0; ni < 8; ni++)
#pragma unroll
            for (int k = 0; k < 4; k++) acc[mi][ni][k] = 0.f;

    sim_prefetch(stA[0], stB[0], r0, c0, 0, tid);  CP_COMMIT();
    sim_prefetch(stA[1], stB[1], r0, c0, 32, tid); CP_COMMIT();
    sim_prefetch(stA[2], stB[2], r0, c0, 64, tid); CP_COMMIT();

    for (int kc = 0; kc < NUM_CHUNKS; kc++) {
        CP_WAIT(2);
        __syncthreads();
        if (kc + 3 < NUM_CHUNKS) {
            const int s = (kc + 3) % SSTAGES;
            sim_prefetch(stA[s], stB[s], r0, c0, (kc + 3) * 32, tid);
        }
        CP_COMMIT();

        const int s = kc % SSTAGES;
#pragma unroll
        for (int ks = 0; ks < 2; ks++) {
            const uint32_t kofs = ks * 32;
            uint32_t aF[4][4], bF[4][4];
#pragma unroll
            for (int mi = 0; mi < 4; mi++)
                ldsm_x4(aF[mi][0], aF[mi][1], aF[mi][2], aF[mi][3],
                        stA[s] + aOff + mi * 16 * ROW_BYTES + kofs);
#pragma unroll
            for (int p = 0; p < 4; p++)
                ldsm_x4(bF[p][0], bF[p][1], bF[p][2], bF[p][3],
                        stB[s] + bOff + p * 16 * ROW_BYTES + kofs);
#pragma unroll
            for (int mi = 0; mi < 4; mi++)
#pragma unroll
                for (int ni = 0; ni < 8; ni++)
                    mma_bf16(acc[mi][ni], aF[mi], &bF[ni >> 1][(ni & 1) * 2]);
        }
    }

    // ---------------- fused epilogue ----------------
    const bool isDiag = (bx == by);
    const bool hasPos = (bx == (by ^ 32));
    const int rb = r0 + warp_m * 64 + (lane >> 2);
    const int cb = c0 + warp_n * 64 + (lane & 3) * 2;

#pragma unroll
    for (int mi = 0; mi < 4; mi++)
#pragma unroll
        for (int ni = 0; ni < 8; ni++)
#pragma unroll
            for (int k = 0; k < 4; k++) {
                const int r = rb + mi * 16 + (k >> 1) * 8;
                const int c = cb + ni * 8 + (k & 1);
                const float logit = acc[mi][ni][k] * 10.0f;
                if (hasPos && c == (r ^ 4096)) { g_pos[r] = logit; g_pos[c] = logit; }
                float ev = __expf(logit - 10.0f);
                if (isDiag && r == c) ev = 0.f;
                acc[mi][ni][k] = ev;
            }

    // row sums: reduce over lane&3 (col quads)
    float rs[4][2];
#pragma unroll
    for (int mi = 0; mi < 4; mi++) { rs[mi][0] = 0.f; rs[mi][1] = 0.f; }
#pragma unroll
    for (int mi = 0; mi < 4; mi++)
#pragma unroll
        for (int ni = 0; ni < 8; ni++) {
            rs[mi][0] += acc[mi][ni][0] + acc[mi][ni][1];
            rs[mi][1] += acc[mi][ni][2] + acc[mi][ni][3];
        }
#pragma unroll
    for (int off = 1; off <= 2; off <<= 1)
#pragma unroll
        for (int mi = 0; mi < 4; mi++)
#pragma unroll
            for (int h = 0; h < 2; h++)
                rs[mi][h] += __shfl_xor_sync(0xffffffffu, rs[mi][h], off);
    {
        const int mi = lane & 3;             // each quad-lane handles one mi
        const int r = r0 + warp_m * 64 + mi * 16 + (lane >> 2);
        atomicAdd(&g_rowsum[r],     rs[mi][0]);
        atomicAdd(&g_rowsum[r + 8], rs[mi][1]);
    }

    // column sums (symmetric contribution), off-diag blocks only
    if (!isDiag) {
        float cs[8][2];
#pragma unroll
        for (int ni = 0; ni < 8; ni++) {
            cs[ni][0] = 0.f; cs[ni][1] = 0.f;
#pragma unroll
            for (int mi = 0; mi < 4; mi++) {
                cs[ni][0] += acc[mi][ni][0] + acc[mi][ni][2];
                cs[ni][1] += acc[mi][ni][1] + acc[mi][ni][3];
            }
        }
#pragma unroll
        for (int off = 4; off <= 16; off <<= 1)
#pragma unroll
            for (int ni = 0; ni < 8; ni++)
#pragma unroll
                for (int h = 0; h < 2; h++)
                    cs[ni][h] += __shfl_xor_sync(0xffffffffu, cs[ni][h], off);
        const int ni = lane >> 2;
        atomicAdd(&g_rowsum[cb + ni * 8 + 0], cs[ni][0]);
        atomicAdd(&g_rowsum[cb + ni * 8 + 1], cs[ni][1]);
    }
}

// ---------------------------------------------------------------------------
// Kernel 4: nll_i = -pos_i + 10 + log(rowsum_i); out = mean(nll)
// ---------------------------------------------------------------------------
__global__ __launch_bounds__(256) void final_kernel(float* __restrict__ out) {
    __shared__ float red[256];
    float s = 0.f;
    for (int i = threadIdx.x; i < NB; i += 256)
        s += -g_pos[i] + 10.0f + logf(g_rowsum[i]);
    red[threadIdx.x] = s;
    __syncthreads();
    for (int off = 128; off > 0; off >>= 1) {
        if (threadIdx.x < off) red[threadIdx.x] += red[threadIdx.x + off];
        __syncthreads();
    }
    if (threadIdx.x == 0) out[0] = red[0] / (float)NB;
}

// ---------------------------------------------------------------------------
extern "C" void kernel_launch(void* const* d_in, const int* in_sizes, int n_in,
                              void* d_out, int out_size) {
    const float* x = (const float*)d_in[0];
    const float* w = (const float*)d_in[1];
    const float* b = (const float*)d_in[2];
    float* out = (float*)d_out;

    cudaFuncSetAttribute(proj_kernel, cudaFuncAttributeMaxDynamicSharedMemorySize, PROJ_SMEM);
    cudaFuncSetAttribute(sim_kernel,  cudaFuncAttributeMaxDynamicSharedMemorySize, SIM_SMEM);

    convert_kernel<<<XCVT_BLOCKS + WCVT_BLOCKS, 256>>>(x, w);
    dim3 g1(P_DIM / 128, M2 / 128);          // 4 x 128
    proj_kernel<<<g1, 128, PROJ_SMEM>>>(b);
    norm_kernel<<<NB, 256>>>();
    sim_kernel<<<TRI_BLOCKS, 128, SIM_SMEM>>>();
    final_kernel<<<1, 256>>>(out);
}

// round 7
// speedup vs baseline: 12.8012x; 1.1530x over previous
#include <cuda_runtime.h>
#include <cuda_bf16.h>
#include <math.h>
#include <stdint.h>

#define NB       8192      // batch B
#define E_DIM    1024
#define P_DIM    512
#define D_DIM    1024      // 2P
#define M2       16384     // 2B rows in projection GEMM

// Scratch (no allocations allowed)
__device__ float g_zn[(size_t)NB * D_DIM];              // 32 MB fp32 (proj output)
__device__ __nv_bfloat16 g_znh[(size_t)NB * D_DIM];     // 16 MB bf16 normalized
__device__ __nv_bfloat16 g_xh[(size_t)NB * 2 * E_DIM];  // 32 MB bf16 relu(x)
__device__ __nv_bfloat16 g_wh[(size_t)E_DIM * P_DIM];   // 1 MB bf16 w
__device__ float g_rowsum[NB];
__device__ float g_pos[NB];

// ---------------------------------------------------------------------------
// PTX helpers (sm_80-era only)
// ---------------------------------------------------------------------------
__device__ __forceinline__ uint32_t smem_u32(const void* p) {
    uint32_t a;
    asm("{ .reg .u64 t; cvta.to.shared.u64 t, %1; cvt.u32.u64 %0, t; }" : "=r"(a) : "l"(p));
    return a;
}
__device__ __forceinline__ void cp_async16(uint32_t dst, const void* src) {
    asm volatile("cp.async.cg.shared.global [%0], [%1], 16;" :: "r"(dst), "l"(src));
}
#define CP_COMMIT() asm volatile("cp.async.commit_group;" ::: "memory")
#define CP_WAIT(N)  asm volatile("cp.async.wait_group %0;" :: "n"(N) : "memory")

__device__ __forceinline__ void ldsm_x4(uint32_t& r0, uint32_t& r1, uint32_t& r2,
                                        uint32_t& r3, uint32_t addr) {
    asm volatile("ldmatrix.sync.aligned.m8n8.x4.shared.b16 {%0,%1,%2,%3}, [%4];"
                 : "=r"(r0), "=r"(r1), "=r"(r2), "=r"(r3) : "r"(addr));
}
__device__ __forceinline__ void ldsm_x4_t(uint32_t& r0, uint32_t& r1, uint32_t& r2,
                                          uint32_t& r3, uint32_t addr) {
    asm volatile("ldmatrix.sync.aligned.m8n8.x4.trans.shared.b16 {%0,%1,%2,%3}, [%4];"
                 : "=r"(r0), "=r"(r1), "=r"(r2), "=r"(r3) : "r"(addr));
}
__device__ __forceinline__ void mma_bf16(float* c, const uint32_t* a, const uint32_t* b) {
    asm volatile(
        "mma.sync.aligned.m16n8k16.row.col.f32.bf16.bf16.f32 "
        "{%0,%1,%2,%3}, {%4,%5,%6,%7}, {%8,%9}, {%0,%1,%2,%3};"
        : "+f"(c[0]), "+f"(c[1]), "+f"(c[2]), "+f"(c[3])
        : "r"(a[0]), "r"(a[1]), "r"(a[2]), "r"(a[3]), "r"(b[0]), "r"(b[1]));
}

// ---------------------------------------------------------------------------
// Kernel 0: convert relu(x)->bf16 (g_xh) and w->bf16 (g_wh)
// ---------------------------------------------------------------------------
#define XCVT_BLOCKS 16384
#define WCVT_BLOCKS 512
__global__ __launch_bounds__(256) void convert_kernel(const float* __restrict__ x,
                                                      const float* __restrict__ w) {
    const int tid = threadIdx.x;
    if (blockIdx.x < XCVT_BLOCKS) {
        const size_t i = ((size_t)blockIdx.x * 256 + tid);
        float4 v = *(const float4*)(x + i * 4);
        __nv_bfloat162 p0 = __floats2bfloat162_rn(fmaxf(v.x, 0.f), fmaxf(v.y, 0.f));
        __nv_bfloat162 p1 = __floats2bfloat162_rn(fmaxf(v.z, 0.f), fmaxf(v.w, 0.f));
        uint2 o; o.x = *(uint32_t*)&p0; o.y = *(uint32_t*)&p1;
        *(uint2*)(g_xh + i * 4) = o;
    } else {
        const size_t i = ((size_t)(blockIdx.x - XCVT_BLOCKS) * 256 + tid);
        float4 v = *(const float4*)(w + i * 4);
        __nv_bfloat162 p0 = __floats2bfloat162_rn(v.x, v.y);
        __nv_bfloat162 p1 = __floats2bfloat162_rn(v.z, v.w);
        uint2 o; o.x = *(uint32_t*)&p0; o.y = *(uint32_t*)&p1;
        *(uint2*)(g_wh + i * 4) = o;
    }
}

// ---------------------------------------------------------------------------
// Kernel 1: HMMA projection, block 128x128, 4 warps (warp tile 64x64),
// BK=32, 4-stage cp.async, single-sync mainloop, batched fragment loads.
// ---------------------------------------------------------------------------
#define AROW_BYTES  80
#define PA_BYTES    (128 * AROW_BYTES)       // 10240
#define BROW_BYTES  272                      // 128 bf16 + 16B pad
#define PB_BYTES    (32 * BROW_BYTES)        // 8704
#define PSTAGE      (PA_BYTES + PB_BYTES)    // 18944
#define PSTAGES     4
#define PROJ_SMEM   (PSTAGES * PSTAGE)       // 75776
#define PCHUNKS     (E_DIM / 32)             // 32

extern __shared__ char dsmem[];

__device__ __forceinline__ void proj_prefetch(uint32_t stA, uint32_t stB,
                                              int m0, int n0, int kb, int tid) {
#pragma unroll
    for (int it = 0; it < 4; it++) {        // A: 128 rows x 4 segs
        const int j = tid + it * 128;
        const int row = j >> 2, seg = j & 3;
        const int r = m0 + row;
        const __nv_bfloat16* src = g_xh + (size_t)(r & (NB - 1)) * 2048
                                 + (size_t)(r >> 13) * 1024 + kb + (seg << 3);
        cp_async16(stA + row * AROW_BYTES + seg * 16, src);
    }
#pragma unroll
    for (int it = 0; it < 4; it++) {        // B: 32 k-rows x 16 segs
        const int j = tid + it * 128;
        const int row = j >> 4, seg = j & 15;
        const __nv_bfloat16* src = g_wh + (size_t)(kb + row) * P_DIM + n0 + (seg << 3);
        cp_async16(stB + row * BROW_BYTES + seg * 16, src);
    }
}

__global__ __launch_bounds__(128)
void proj_kernel(const float* __restrict__ bias) {
    const int tid = threadIdx.x;
    const int wid = tid >> 5;
    const int lane = tid & 31;
    const int warp_m = wid >> 1;
    const int warp_n = wid & 1;
    const int m0 = blockIdx.y * 128;
    const int n0 = blockIdx.x * 128;

    const uint32_t sbase = smem_u32(dsmem);
    uint32_t stA[PSTAGES], stB[PSTAGES];
#pragma unroll
    for (int s = 0; s < PSTAGES; s++) {
        stA[s] = sbase + s * PSTAGE;
        stB[s] = stA[s] + PA_BYTES;
    }

    const uint32_t aOff = (warp_m * 64 + (lane & 15)) * AROW_BYTES + (lane >> 4) * 16;
    const uint32_t bRow = (lane & 7) + ((lane >> 3) & 1) * 8;
    const uint32_t bCol = warp_n * 64 + (lane >> 4) * 8;

    float acc[4][8][4];
#pragma unroll
    for (int mi = 0; mi < 4; mi++)
#pragma unroll
        for (int ni = 0; ni < 8; ni++)
#pragma unroll
            for (int k = 0; k < 4; k++) acc[mi][ni][k] = 0.f;

    proj_prefetch(stA[0], stB[0], m0, n0, 0, tid);  CP_COMMIT();
    proj_prefetch(stA[1], stB[1], m0, n0, 32, tid); CP_COMMIT();
    proj_prefetch(stA[2], stB[2], m0, n0, 64, tid); CP_COMMIT();

    for (int kc = 0; kc < PCHUNKS; kc++) {
        CP_WAIT(2);
        __syncthreads();
        const int s = kc % PSTAGES;

        // batched fragment loads (both ks halves) - issue ALL before mma
        uint32_t aF[2][4][4], bF[2][4][4];
#pragma unroll
        for (int ks = 0; ks < 2; ks++) {
#pragma unroll
            for (int mi = 0; mi < 4; mi++)
                ldsm_x4(aF[ks][mi][0], aF[ks][mi][1], aF[ks][mi][2], aF[ks][mi][3],
                        stA[s] + aOff + mi * 16 * AROW_BYTES + ks * 32);
#pragma unroll
            for (int p = 0; p < 4; p++)
                ldsm_x4_t(bF[ks][p][0], bF[ks][p][1], bF[ks][p][2], bF[ks][p][3],
                          stB[s] + (ks * 16 + bRow) * BROW_BYTES + (bCol + p * 16) * 2);
        }

        if (kc + 3 < PCHUNKS) {
            const int sn = (kc + 3) % PSTAGES;
            proj_prefetch(stA[sn], stB[sn], m0, n0, (kc + 3) * 32, tid);
        }
        CP_COMMIT();

#pragma unroll
        for (int ks = 0; ks < 2; ks++)
#pragma unroll
            for (int mi = 0; mi < 4; mi++)
#pragma unroll
                for (int ni = 0; ni < 8; ni++)
                    mma_bf16(acc[mi][ni], aF[ks][mi], &bF[ks][ni >> 1][(ni & 1) * 2]);
    }

    // epilogue: + bias, store fp32 to g_zn (interleaved layout)
    const int cb = n0 + warp_n * 64 + (lane & 3) * 2;
#pragma unroll
    for (int mi = 0; mi < 4; mi++)
#pragma unroll
        for (int half8 = 0; half8 < 2; half8++) {
            const int r = m0 + warp_m * 64 + mi * 16 + half8 * 8 + (lane >> 2);
            const int ib = r & (NB - 1);
            const int hh = r >> 13;
            float* outRow = g_zn + (size_t)ib * D_DIM + hh * P_DIM;
#pragma unroll
            for (int ni = 0; ni < 8; ni++) {
                const int c = cb + ni * 8;
                float2 v;
                v.x = acc[mi][ni][half8 * 2 + 0] + __ldg(bias + c);
                v.y = acc[mi][ni][half8 * 2 + 1] + __ldg(bias + c + 1);
                *(float2*)(outRow + c) = v;
            }
        }
}

// ---------------------------------------------------------------------------
// Kernel 2: per-row L2 normalize -> bf16 g_znh (also zeroes g_rowsum)
// ---------------------------------------------------------------------------
__global__ __launch_bounds__(256) void norm_kernel() {
    __shared__ float red[256];
    const float* row = g_zn + (size_t)blockIdx.x * D_DIM;
    float4 v = *(const float4*)(row + threadIdx.x * 4);
    red[threadIdx.x] = v.x * v.x + v.y * v.y + v.z * v.z + v.w * v.w;
    __syncthreads();
    for (int off = 128; off > 0; off >>= 1) {
        if (threadIdx.x < off) red[threadIdx.x] += red[threadIdx.x + off];
        __syncthreads();
    }
    const float inv = 1.0f / fmaxf(sqrtf(red[0]), 1e-8f);
    __nv_bfloat162 p0 = __floats2bfloat162_rn(v.x * inv, v.y * inv);
    __nv_bfloat162 p1 = __floats2bfloat162_rn(v.z * inv, v.w * inv);
    uint2 o; o.x = *(uint32_t*)&p0; o.y = *(uint32_t*)&p1;
    *(uint2*)(g_znh + (size_t)blockIdx.x * D_DIM + threadIdx.x * 4) = o;
    if (threadIdx.x == 0) g_rowsum[blockIdx.x] = 0.f;
}

// ---------------------------------------------------------------------------
// Kernel 3: HMMA sim GEMM (upper triangle), block 128x128, 4 warps (64x64),
// 4-stage cp.async, batched fragment loads, fused softmax partials.
// ---------------------------------------------------------------------------
#define ROW_BYTES   80
#define TILE_BYTES  (128 * ROW_BYTES)
#define STAGE_BYTES (2 * TILE_BYTES)
#define SSTAGES     4
#define SIM_SMEM    (SSTAGES * STAGE_BYTES)  // 81920
#define NUM_CHUNKS  (D_DIM / 32)
#define TRI_BLOCKS  2080

__device__ __forceinline__ void sim_prefetch(uint32_t stageA, uint32_t stageB,
                                             int r0, int c0, int kb, int tid) {
#pragma unroll
    for (int it = 0; it < 4; it++) {
        const int i = tid + it * 128;
        const int row = i >> 2, seg = i & 3;
        const uint32_t d = row * ROW_BYTES + seg * 16;
        cp_async16(stageA + d, g_znh + (((size_t)(r0 + row)) << 10) + kb + (seg << 3));
        cp_async16(stageB + d, g_znh + (((size_t)(c0 + row)) << 10) + kb + (seg << 3));
    }
}

__global__ __launch_bounds__(128)
void sim_kernel() {
    // map t -> (by, bx) upper triangle, bx >= by
    const int t = blockIdx.x;
    int by = (int)((129.0f - sqrtf(129.0f * 129.0f - 8.0f * (float)t)) * 0.5f);
    if (by > 63) by = 63;
    if (by < 0) by = 0;
    while (by * 64 - (by * (by - 1)) / 2 > t) by--;
    while ((by + 1) * 64 - ((by + 1) * by) / 2 <= t) by++;
    const int bx = by + (t - (by * 64 - (by * (by - 1)) / 2));

    const int tid = threadIdx.x;
    const int wid = tid >> 5;
    const int lane = tid & 31;
    const int warp_m = wid >> 1;
    const int warp_n = wid & 1;
    const int r0 = by * 128;
    const int c0 = bx * 128;

    const uint32_t sbase = smem_u32(dsmem);
    uint32_t stA[SSTAGES], stB[SSTAGES];
#pragma unroll
    for (int s = 0; s < SSTAGES; s++) {
        stA[s] = sbase + s * STAGE_BYTES;
        stB[s] = stA[s] + TILE_BYTES;
    }

    const uint32_t aOff = (warp_m * 64 + (lane & 15)) * ROW_BYTES + (lane >> 4) * 16;
    const uint32_t bOff = (warp_n * 64 + ((lane >> 4) & 1) * 8 + (lane & 7)) * ROW_BYTES
                        + ((lane >> 3) & 1) * 16;

    float acc[4][8][4];
#pragma unroll
    for (int mi = 0; mi < 4; mi++)
#pragma unroll
        for (int ni = 0; ni < 8; ni++)
#pragma unroll
            for (int k = 0; k < 4; k++) acc[mi][ni][k] = 0.f;

    sim_prefetch(stA[0], stB[0], r0, c0, 0, tid);  CP_COMMIT();
    sim_prefetch(stA[1], stB[1], r0, c0, 32, tid); CP_COMMIT();
    sim_prefetch(stA[2], stB[2], r0, c0, 64, tid); CP_COMMIT();

    for (int kc = 0; kc < NUM_CHUNKS; kc++) {
        CP_WAIT(2);
        __syncthreads();
        const int s = kc % SSTAGES;

        // batched fragment loads (both ks halves) - issue ALL before mma
        uint32_t aF[2][4][4], bF[2][4][4];
#pragma unroll
        for (int ks = 0; ks < 2; ks++) {
#pragma unroll
            for (int mi = 0; mi < 4; mi++)
                ldsm_x4(aF[ks][mi][0], aF[ks][mi][1], aF[ks][mi][2], aF[ks][mi][3],
                        stA[s] + aOff + mi * 16 * ROW_BYTES + ks * 32);
#pragma unroll
            for (int p = 0; p < 4; p++)
                ldsm_x4(bF[ks][p][0], bF[ks][p][1], bF[ks][p][2], bF[ks][p][3],
                        stB[s] + bOff + p * 16 * ROW_BYTES + ks * 32);
        }

        if (kc + 3 < NUM_CHUNKS) {
            const int sn = (kc + 3) % SSTAGES;
            sim_prefetch(stA[sn], stB[sn], r0, c0, (kc + 3) * 32, tid);
        }
        CP_COMMIT();

#pragma unroll
        for (int ks = 0; ks < 2; ks++)
#pragma unroll
            for (int mi = 0; mi < 4; mi++)
#pragma unroll
                for (int ni = 0; ni < 8; ni++)
                    mma_bf16(acc[mi][ni], aF[ks][mi], &bF[ks][ni >> 1][(ni & 1) * 2]);
    }

    // ---------------- fused epilogue ----------------
    const bool isDiag = (bx == by);
    const bool hasPos = (bx == (by ^ 32));
    const int rb = r0 + warp_m * 64 + (lane >> 2);
    const int cb = c0 + warp_n * 64 + (lane & 3) * 2;

#pragma unroll
    for (int mi = 0; mi < 4; mi++)
#pragma unroll
        for (int ni = 0; ni < 8; ni++)
#pragma unroll
            for (int k = 0; k < 4; k++) {
                const int r = rb + mi * 16 + (k >> 1) * 8;
                const int c = cb + ni * 8 + (k & 1);
                const float logit = acc[mi][ni][k] * 10.0f;
                if (hasPos && c == (r ^ 4096)) { g_pos[r] = logit; g_pos[c] = logit; }
                float ev = __expf(logit - 10.0f);
                if (isDiag && r == c) ev = 0.f;
                acc[mi][ni][k] = ev;
            }

    // row sums
    float rs[4][2];
#pragma unroll
    for (int mi = 0; mi < 4; mi++) { rs[mi][0] = 0.f; rs[mi][1] = 0.f; }
#pragma unroll
    for (int mi = 0; mi < 4; mi++)
#pragma unroll
        for (int ni = 0; ni < 8; ni++) {
            rs[mi][0] += acc[mi][ni][0] + acc[mi][ni][1];
            rs[mi][1] += acc[mi][ni][2] + acc[mi][ni][3];
        }
#pragma unroll
    for (int off = 1; off <= 2; off <<= 1)
#pragma unroll
        for (int mi = 0; mi < 4; mi++)
#pragma unroll
            for (int h = 0; h < 2; h++)
                rs[mi][h] += __shfl_xor_sync(0xffffffffu, rs[mi][h], off);
    {
        const int mi = lane & 3;
        const int r = r0 + warp_m * 64 + mi * 16 + (lane >> 2);
        atomicAdd(&g_rowsum[r],     rs[mi][0]);
        atomicAdd(&g_rowsum[r + 8], rs[mi][1]);
    }

    // column sums (symmetric contribution), off-diag blocks only
    if (!isDiag) {
        float cs[8][2];
#pragma unroll
        for (int ni = 0; ni < 8; ni++) {
            cs[ni][0] = 0.f; cs[ni][1] = 0.f;
#pragma unroll
            for (int mi = 0; mi < 4; mi++) {
                cs[ni][0] += acc[mi][ni][0] + acc[mi][ni][2];
                cs[ni][1] += acc[mi][ni][1] + acc[mi][ni][3];
            }
        }
#pragma unroll
        for (int off = 4; off <= 16; off <<= 1)
#pragma unroll
            for (int ni = 0; ni < 8; ni++)
#pragma unroll
                for (int h = 0; h < 2; h++)
                    cs[ni][h] += __shfl_xor_sync(0xffffffffu, cs[ni][h], off);
        const int ni = lane >> 2;
        atomicAdd(&g_rowsum[cb + ni * 8 + 0], cs[ni][0]);
        atomicAdd(&g_rowsum[cb + ni * 8 + 1], cs[ni][1]);
    }
}

// ---------------------------------------------------------------------------
// Kernel 4: nll_i = -pos_i + 10 + log(rowsum_i); out = mean(nll)
// ---------------------------------------------------------------------------
__global__ __launch_bounds__(256) void final_kernel(float* __restrict__ out) {
    __shared__ float red[256];
    float s = 0.f;
    for (int i = threadIdx.x; i < NB; i += 256)
        s += -g_pos[i] + 10.0f + logf(g_rowsum[i]);
    red[threadIdx.x] = s;
    __syncthreads();
    for (int off = 128; off > 0; off >>= 1) {
        if (threadIdx.x < off) red[threadIdx.x] += red[threadIdx.x + off];
        __syncthreads();
    }
    if (threadIdx.x == 0) out[0] = red[0] / (float)NB;
}

// ---------------------------------------------------------------------------
extern "C" void kernel_launch(void* const* d_in, const int* in_sizes, int n_in,
                              void* d_out, int out_size) {
    const float* x = (const float*)d_in[0];
    const float* w = (const float*)d_in[1];
    const float* b = (const float*)d_in[2];
    float* out = (float*)d_out;

    cudaFuncSetAttribute(proj_kernel, cudaFuncAttributeMaxDynamicSharedMemorySize, PROJ_SMEM);
    cudaFuncSetAttribute(sim_kernel,  cudaFuncAttributeMaxDynamicSharedMemorySize, SIM_SMEM);

    convert_kernel<<<XCVT_BLOCKS + WCVT_BLOCKS, 256>>>(x, w);
    dim3 g1(P_DIM / 128, M2 / 128);
    proj_kernel<<<g1, 128, PROJ_SMEM>>>(b);
    norm_kernel<<<NB, 256>>>();
    sim_kernel<<<TRI_BLOCKS, 128, SIM_SMEM>>>();
    final_kernel<<<1, 256>>>(out);
}